// round 4
// baseline (speedup 1.0000x reference)
#include <cuda_runtime.h>
#include <math.h>

#define NMAX 100000
#define EMAX 1000000

// ---------------- scratch (static device arrays; no allocation) ----------------
__device__ float4 g_h4[(size_t)NMAX * 32];        // h [N,128] as float4
__device__ float4 g_asrc4[NMAX];                  // a_src [N,4]
__device__ float4 g_adst4[NMAX];                  // a_dst [N,4]
__device__ int    g_cnt[NMAX];                    // in-degree counts
__device__ int    g_rowptr[NMAX + 1];             // CSR row pointers (by dst)
__device__ int    g_cur[NMAX];                    // fill cursors
__device__ int    g_part[256];                    // scan block partials
__device__ int    g_adj[EMAX];                    // adjacency: src ids grouped by dst
__device__ int    g_is64;                         // edge_index dtype flag

// ---------------- helpers ----------------
__device__ __forceinline__ int load_idx(const void* ei, long long i, int is64) {
    if (is64) return (int)((const long long*)ei)[i];
    return ((const int*)ei)[i];
}
__device__ __forceinline__ float lrelu(float v) { return v >= 0.f ? v : 0.2f * v; }

#define FMA2(a, xx, ww) asm("fma.rn.f32x2 %0, %1, %2, %0;" : "+l"(a) : "l"(xx), "l"(ww))

// ---------------- init: zero counts + dtype detect ----------------
__global__ void k_init(const void* ei, int n) {
    int i = blockIdx.x * blockDim.x + threadIdx.x;
    if (i < n) g_cnt[i] = 0;
    if (i == 0) {
        const long long* p = (const long long*)ei;
        int ok = 1;
        for (int j = 0; j < 8; j++) {
            long long v = p[j];
            if (v < 0 || v >= n) ok = 0;
        }
        g_is64 = ok;
    }
}

// ---------------- tiled SGEMM: h = x @ W ----------------
// Tile: 64 rows x 128 cols per block, 256 threads, 4x8 register blocking.
// x staged transposed + duplicated ({x,x} u64) so f32x2 FMA needs no packing.
// Row stride 66 u64 = 528 B: multiple of 16 so ulonglong2 LDS stay aligned
// (stride 129 -> 1032 B traps on odd k: 1032 % 16 = 8).
#define GR 64
#define XSTR 66
__global__ void __launch_bounds__(256) k_gemm(
    const float* __restrict__ x, const float* __restrict__ W, int n)
{
    extern __shared__ char smraw[];
    unsigned long long* sxd = (unsigned long long*)smraw;      // [128][XSTR] u64
    float* sw = (float*)(smraw + 128 * XSTR * 8);              // [128][128] f32
    const int tid = threadIdx.x;
    const int rowbase = blockIdx.x * GR;

    // stage W (linear copy, 64KB)
    {
        const float4* W4 = (const float4*)W;
        float4* s4 = (float4*)sw;
        for (int i = tid; i < 128 * 32; i += 256) s4[i] = W4[i];
    }
    // stage x tile transposed + duplicated
    for (int i = tid; i < GR * 32; i += 256) {
        int row = i >> 5, k4 = i & 31;
        int grow = min(rowbase + row, n - 1);
        float4 v = ((const float4*)(x + (size_t)grow * 128))[k4];
        unsigned long long d;
        asm("mov.b64 %0, {%1, %1};" : "=l"(d) : "f"(v.x)); sxd[(k4 * 4 + 0) * XSTR + row] = d;
        asm("mov.b64 %0, {%1, %1};" : "=l"(d) : "f"(v.y)); sxd[(k4 * 4 + 1) * XSTR + row] = d;
        asm("mov.b64 %0, {%1, %1};" : "=l"(d) : "f"(v.z)); sxd[(k4 * 4 + 2) * XSTR + row] = d;
        asm("mov.b64 %0, {%1, %1};" : "=l"(d) : "f"(v.w)); sxd[(k4 * 4 + 3) * XSTR + row] = d;
    }
    __syncthreads();

    const int r0 = (tid >> 4) * 4;     // 0..60 (multiple of 4 -> 32B aligned u64 pairs)
    const int c0 = (tid & 15) * 8;     // 0..120 (multiple of 8 -> 32B aligned f32 quads)
    unsigned long long acc[4][4];
#pragma unroll
    for (int r = 0; r < 4; r++)
#pragma unroll
        for (int c = 0; c < 4; c++) acc[r][c] = 0ull;

#pragma unroll 8
    for (int k = 0; k < 128; k++) {
        ulonglong2 xa = *(const ulonglong2*)&sxd[k * XSTR + r0];      // rows r0, r0+1
        ulonglong2 xb = *(const ulonglong2*)&sxd[k * XSTR + r0 + 2];  // rows r0+2, r0+3
        ulonglong2 wa = *(const ulonglong2*)&sw[k * 128 + c0];        // colpairs 0,1
        ulonglong2 wb = *(const ulonglong2*)&sw[k * 128 + c0 + 4];    // colpairs 2,3
        FMA2(acc[0][0], xa.x, wa.x); FMA2(acc[0][1], xa.x, wa.y);
        FMA2(acc[0][2], xa.x, wb.x); FMA2(acc[0][3], xa.x, wb.y);
        FMA2(acc[1][0], xa.y, wa.x); FMA2(acc[1][1], xa.y, wa.y);
        FMA2(acc[1][2], xa.y, wb.x); FMA2(acc[1][3], xa.y, wb.y);
        FMA2(acc[2][0], xb.x, wa.x); FMA2(acc[2][1], xb.x, wa.y);
        FMA2(acc[2][2], xb.x, wb.x); FMA2(acc[2][3], xb.x, wb.y);
        FMA2(acc[3][0], xb.y, wa.x); FMA2(acc[3][1], xb.y, wa.y);
        FMA2(acc[3][2], xb.y, wb.x); FMA2(acc[3][3], xb.y, wb.y);
    }

#pragma unroll
    for (int r = 0; r < 4; r++) {
        int grow = rowbase + r0 + r;
        if (grow < n) {
            float4 o1, o2;
            asm("mov.b64 {%0, %1}, %2;" : "=f"(o1.x), "=f"(o1.y) : "l"(acc[r][0]));
            asm("mov.b64 {%0, %1}, %2;" : "=f"(o1.z), "=f"(o1.w) : "l"(acc[r][1]));
            asm("mov.b64 {%0, %1}, %2;" : "=f"(o2.x), "=f"(o2.y) : "l"(acc[r][2]));
            asm("mov.b64 {%0, %1}, %2;" : "=f"(o2.z), "=f"(o2.w) : "l"(acc[r][3]));
            g_h4[(size_t)grow * 32 + (c0 >> 2)] = o1;
            g_h4[(size_t)grow * 32 + (c0 >> 2) + 1] = o2;
        }
    }
}

// ---------------- attention dots: a_src/a_dst from h ----------------
__global__ void __launch_bounds__(256) k_att(
    const float* __restrict__ att_src, const float* __restrict__ att_dst, int n)
{
    const int lane = threadIdx.x & 31;
    const int i = (blockIdx.x * blockDim.x + threadIdx.x) >> 5;
    if (i >= n) return;
    float4 as4 = ((const float4*)att_src)[lane];
    float4 ad4 = ((const float4*)att_dst)[lane];
    float4 h4 = g_h4[(size_t)i * 32 + lane];
    float ps = h4.x * as4.x + h4.y * as4.y + h4.z * as4.z + h4.w * as4.w;
    float pd = h4.x * ad4.x + h4.y * ad4.y + h4.z * ad4.z + h4.w * ad4.w;
    const unsigned FULL = 0xffffffffu;
    ps += __shfl_xor_sync(FULL, ps, 4);
    pd += __shfl_xor_sync(FULL, pd, 4);
    ps += __shfl_xor_sync(FULL, ps, 2);
    pd += __shfl_xor_sync(FULL, pd, 2);
    ps += __shfl_xor_sync(FULL, ps, 1);
    pd += __shfl_xor_sync(FULL, pd, 1);
    if ((lane & 7) == 0) {
        ((float*)g_asrc4)[i * 4 + (lane >> 3)] = ps;
        ((float*)g_adst4)[i * 4 + (lane >> 3)] = pd;
    }
}

// ---------------- CSR build: histogram ----------------
__global__ void k_hist(const void* __restrict__ ei, int E) {
    int e = blockIdx.x * blockDim.x + threadIdx.x;
    if (e >= E) return;
    int dst = load_idx(ei, (long long)E + e, g_is64);
    atomicAdd(&g_cnt[dst], 1);
}

// ---------------- CSR build: scan (3 phases) ----------------
#define SCAN_BLK 1024
__global__ void k_scan1(int n) {
    __shared__ int sred[256];
    int b = blockIdx.x, t = threadIdx.x;
    int base = b * SCAN_BLK + t * 4;
    int s = 0;
#pragma unroll
    for (int u = 0; u < 4; u++) { int idx = base + u; if (idx < n) s += g_cnt[idx]; }
    sred[t] = s; __syncthreads();
    for (int off = 128; off > 0; off >>= 1) {
        if (t < off) sred[t] += sred[t + off];
        __syncthreads();
    }
    if (t == 0) g_part[b] = sred[0];
}
__global__ void k_scan2(int nb) {
    __shared__ int sp[128];
    int t = threadIdx.x;
    int v = (t < nb) ? g_part[t] : 0;
    sp[t] = v; __syncthreads();
    for (int off = 1; off < 128; off <<= 1) {
        int u = (t >= off) ? sp[t - off] : 0;
        __syncthreads();
        sp[t] += u;
        __syncthreads();
    }
    if (t < nb) g_part[t] = sp[t] - v;
}
__global__ void k_scan3(int n, int E) {
    __shared__ int ssum[256];
    int b = blockIdx.x, t = threadIdx.x;
    int base = b * SCAN_BLK + t * 4;
    int c[4]; int s = 0;
#pragma unroll
    for (int u = 0; u < 4; u++) { int idx = base + u; c[u] = (idx < n) ? g_cnt[idx] : 0; s += c[u]; }
    ssum[t] = s; __syncthreads();
    for (int off = 1; off < 256; off <<= 1) {
        int u = (t >= off) ? ssum[t - off] : 0;
        __syncthreads();
        ssum[t] += u;
        __syncthreads();
    }
    int run = g_part[b] + ssum[t] - s;
#pragma unroll
    for (int u = 0; u < 4; u++) {
        int idx = base + u;
        if (idx < n) { g_rowptr[idx] = run; g_cur[idx] = run; run += c[u]; }
    }
    if (b == 0 && t == 0) g_rowptr[n] = E;
}

// ---------------- CSR build: fill ----------------
__global__ void k_fill(const void* __restrict__ ei, int E) {
    int e = blockIdx.x * blockDim.x + threadIdx.x;
    if (e >= E) return;
    int is64 = g_is64;
    int src = load_idx(ei, e, is64);
    int dst = load_idx(ei, (long long)E + e, is64);
    int pos = atomicAdd(&g_cur[dst], 1);
    g_adj[pos] = src;
}

// ---------------- fused gather: softmax (no max shift) + aggregation + bias ----------------
// One warp per dst node. Lane l handles output cols 4l..4l+3 (head = l>>3).
// Logits are tiny (|alpha| < ~8) so exp() without max-subtraction is exact-safe.
__global__ void __launch_bounds__(256) k_gather(
    const float* __restrict__ bias, float* __restrict__ out, int n)
{
    __shared__ int   s_src[8][32];
    __shared__ float s_ex[8][32][4];
    const int lane = threadIdx.x & 31;
    const int wslot = threadIdx.x >> 5;
    const int i = (blockIdx.x * blockDim.x + threadIdx.x) >> 5;
    if (i >= n) return;
    const int hidx = lane >> 3;
    const unsigned FULL = 0xffffffffu;

    int start = g_rowptr[i];
    int deg = g_rowptr[i + 1] - start;
    float4 adst = g_adst4[i];

    float4 acc = make_float4(0.f, 0.f, 0.f, 0.f);
    float4 den = make_float4(0.f, 0.f, 0.f, 0.f);
    const float* exf = &s_ex[wslot][0][0];

    for (int base = 0; base < deg; base += 32) {
        int e = base + lane;
        int s = 0;
        float4 ex4 = make_float4(0.f, 0.f, 0.f, 0.f);
        if (e < deg) {
            s = g_adj[start + e];
            float4 as = g_asrc4[s];
            ex4.x = __expf(lrelu(as.x + adst.x));
            ex4.y = __expf(lrelu(as.y + adst.y));
            ex4.z = __expf(lrelu(as.z + adst.z));
            ex4.w = __expf(lrelu(as.w + adst.w));
            den.x += ex4.x; den.y += ex4.y; den.z += ex4.z; den.w += ex4.w;
        }
        s_src[wslot][lane] = s;
        s_ex[wslot][lane][0] = ex4.x; s_ex[wslot][lane][1] = ex4.y;
        s_ex[wslot][lane][2] = ex4.z; s_ex[wslot][lane][3] = ex4.w;
        __syncwarp();

        int cnt = min(32, deg - base);
        int j = 0;
        for (; j + 4 <= cnt; j += 4) {
            int s0 = s_src[wslot][j + 0], s1 = s_src[wslot][j + 1];
            int s2 = s_src[wslot][j + 2], s3 = s_src[wslot][j + 3];
            float w0 = exf[(j + 0) * 4 + hidx], w1 = exf[(j + 1) * 4 + hidx];
            float w2 = exf[(j + 2) * 4 + hidx], w3 = exf[(j + 3) * 4 + hidx];
            float4 h0 = g_h4[(size_t)s0 * 32 + lane];
            float4 h1 = g_h4[(size_t)s1 * 32 + lane];
            float4 h2 = g_h4[(size_t)s2 * 32 + lane];
            float4 h3 = g_h4[(size_t)s3 * 32 + lane];
            acc.x += w0 * h0.x; acc.y += w0 * h0.y; acc.z += w0 * h0.z; acc.w += w0 * h0.w;
            acc.x += w1 * h1.x; acc.y += w1 * h1.y; acc.z += w1 * h1.z; acc.w += w1 * h1.w;
            acc.x += w2 * h2.x; acc.y += w2 * h2.y; acc.z += w2 * h2.z; acc.w += w2 * h2.w;
            acc.x += w3 * h3.x; acc.y += w3 * h3.y; acc.z += w3 * h3.z; acc.w += w3 * h3.w;
        }
        for (; j < cnt; j++) {
            int sj = s_src[wslot][j];
            float w = exf[j * 4 + hidx];
            float4 hv = g_h4[(size_t)sj * 32 + lane];
            acc.x += w * hv.x; acc.y += w * hv.y; acc.z += w * hv.z; acc.w += w * hv.w;
        }
        __syncwarp();
    }

    // self-loop contribution
    float4 exs;
    {
        float4 as = g_asrc4[i];
        exs.x = __expf(lrelu(as.x + adst.x));
        exs.y = __expf(lrelu(as.y + adst.y));
        exs.z = __expf(lrelu(as.z + adst.z));
        exs.w = __expf(lrelu(as.w + adst.w));
    }
    {
        float ws = (hidx == 0) ? exs.x : (hidx == 1) ? exs.y : (hidx == 2) ? exs.z : exs.w;
        float4 hv = g_h4[(size_t)i * 32 + lane];
        acc.x += ws * hv.x; acc.y += ws * hv.y; acc.z += ws * hv.z; acc.w += ws * hv.w;
    }

#pragma unroll
    for (int off = 16; off > 0; off >>= 1) {
        den.x += __shfl_xor_sync(FULL, den.x, off);
        den.y += __shfl_xor_sync(FULL, den.y, off);
        den.z += __shfl_xor_sync(FULL, den.z, off);
        den.w += __shfl_xor_sync(FULL, den.w, off);
    }
    den.x += exs.x; den.y += exs.y; den.z += exs.z; den.w += exs.w;

    float dh = (hidx == 0) ? den.x : (hidx == 1) ? den.y : (hidx == 2) ? den.z : den.w;
    float inv = 1.f / (dh + 1e-16f);
    float4 b4 = ((const float4*)bias)[lane];
    float4 o;
    o.x = acc.x * inv + b4.x; o.y = acc.y * inv + b4.y;
    o.z = acc.z * inv + b4.z; o.w = acc.w * inv + b4.w;
    ((float4*)out)[(size_t)i * 32 + lane] = o;
}

// ---------------- launch ----------------
extern "C" void kernel_launch(void* const* d_in, const int* in_sizes, int n_in,
                              void* d_out, int out_size)
{
    const float* x       = (const float*)d_in[0];
    const void*  ei      = d_in[1];
    const float* W       = (const float*)d_in[2];
    const float* att_src = (const float*)d_in[3];
    const float* att_dst = (const float*)d_in[4];
    const float* bias    = (const float*)d_in[5];
    float* out = (float*)d_out;

    int n = in_sizes[0] / 128;
    int E = in_sizes[1] / 2;
    int nb = (n + SCAN_BLK - 1) / SCAN_BLK;
    const int GEMM_SMEM = 128 * XSTR * 8 + 128 * 128 * 4;   // 67584 + 65536 = 133120

    cudaFuncSetAttribute(k_gemm, cudaFuncAttributeMaxDynamicSharedMemorySize, GEMM_SMEM);

    k_init<<<(n + 255) / 256, 256>>>(ei, n);
    k_gemm<<<(n + GR - 1) / GR, 256, GEMM_SMEM>>>(x, W, n);
    k_att<<<(n * 32 + 255) / 256, 256>>>(att_src, att_dst, n);
    k_hist<<<(E + 255) / 256, 256>>>(ei, E);
    k_scan1<<<nb, 256>>>(n);
    k_scan2<<<1, 128>>>(nb);
    k_scan3<<<nb, 256>>>(n, E);
    k_fill<<<(E + 255) / 256, 256>>>(ei, E);
    k_gather<<<(n + 7) / 8, 256>>>(bias, out, n);
}

// round 5
// speedup vs baseline: 1.1950x; 1.1950x over previous
#include <cuda_runtime.h>
#include <math.h>

#define NMAX 100000
#define EMAX 1000000

// ---------------- scratch (static device arrays; no allocation) ----------------
__device__ float4 g_h4[(size_t)NMAX * 32];        // h [N,128] as float4
__device__ float4 g_asrc4[NMAX];                  // a_src [N,4]
__device__ float4 g_adst4[NMAX];                  // a_dst [N,4]
__device__ int    g_cnt[NMAX];                    // in-degree counts
__device__ int    g_rowptr[NMAX + 1];             // CSR row pointers (by dst)
__device__ int    g_cur[NMAX];                    // fill cursors
__device__ int    g_part[256];                    // scan block partials
__device__ int    g_adj[EMAX];                    // adjacency: src ids grouped by dst
__device__ int    g_is64;                         // edge_index dtype flag

// ---------------- helpers ----------------
__device__ __forceinline__ int load_idx(const void* ei, long long i, int is64) {
    if (is64) return (int)((const long long*)ei)[i];
    return ((const int*)ei)[i];
}
__device__ __forceinline__ float lrelu(float v) { return v >= 0.f ? v : 0.2f * v; }

#define FMA2(a, xx, ww) asm("fma.rn.f32x2 %0, %1, %2, %0;" : "+l"(a) : "l"(xx), "l"(ww))

// ---------------- init: zero counts + dtype detect ----------------
__global__ void k_init(const void* ei, int n) {
    int i = blockIdx.x * blockDim.x + threadIdx.x;
    if (i < n) g_cnt[i] = 0;
    if (i == 0) {
        const long long* p = (const long long*)ei;
        int ok = 1;
        for (int j = 0; j < 8; j++) {
            long long v = p[j];
            if (v < 0 || v >= n) ok = 0;
        }
        g_is64 = ok;
    }
}

// ---------------- tiled SGEMM: h = x @ W ----------------
// 64 rows x 128 cols per block, 256 threads. Thread tile: 8 rows x 4 cols.
// Warp w -> rows w*8..w*8+7 (x reads are pure broadcast, N=1).
// Lane l -> cols l*4..l*4+3 (W reads are per-lane contiguous 16B: the
// canonical conflict-free LDS.128 pattern; warp spans one 512B row).
// x staged transposed + duplicated ({x,x} u64), stride 64 u64 = 512B so all
// 16B accesses stay aligned.
#define GR 64
#define XSTR 64
__global__ void __launch_bounds__(256) k_gemm(
    const float* __restrict__ x, const float* __restrict__ W, int n)
{
    extern __shared__ char smraw[];
    unsigned long long* sxd = (unsigned long long*)smraw;      // [128][XSTR] u64 (64KB)
    float* sw = (float*)(smraw + 128 * XSTR * 8);              // [128][128] f32 (64KB)
    const int tid = threadIdx.x;
    const int rowbase = blockIdx.x * GR;

    // stage W (linear copy, 64KB)
    {
        const float4* W4 = (const float4*)W;
        float4* s4 = (float4*)sw;
        for (int i = tid; i < 128 * 32; i += 256) s4[i] = W4[i];
    }
    // stage x tile transposed + duplicated; row fastest so STS are contiguous
    for (int i = tid; i < GR * 32; i += 256) {
        int row = i & 63, k4 = i >> 6;
        int grow = min(rowbase + row, n - 1);
        float4 v = ((const float4*)(x + (size_t)grow * 128))[k4];
        unsigned long long d;
        asm("mov.b64 %0, {%1, %1};" : "=l"(d) : "f"(v.x)); sxd[(k4 * 4 + 0) * XSTR + row] = d;
        asm("mov.b64 %0, {%1, %1};" : "=l"(d) : "f"(v.y)); sxd[(k4 * 4 + 1) * XSTR + row] = d;
        asm("mov.b64 %0, {%1, %1};" : "=l"(d) : "f"(v.z)); sxd[(k4 * 4 + 2) * XSTR + row] = d;
        asm("mov.b64 %0, {%1, %1};" : "=l"(d) : "f"(v.w)); sxd[(k4 * 4 + 3) * XSTR + row] = d;
    }
    __syncthreads();

    const int lane = tid & 31;
    const int r0 = (tid >> 5) * 8;   // warp-uniform, multiple of 8
    const int c0 = lane * 4;         // per-lane contiguous 16B
    unsigned long long acc[8][2];
#pragma unroll
    for (int r = 0; r < 8; r++) { acc[r][0] = 0ull; acc[r][1] = 0ull; }

#pragma unroll 8
    for (int k = 0; k < 128; k++) {
        ulonglong2 wv = *(const ulonglong2*)&sw[k * 128 + c0];        // 4 cols
        ulonglong2 xa = *(const ulonglong2*)&sxd[k * XSTR + r0];      // rows r0,r0+1
        ulonglong2 xb = *(const ulonglong2*)&sxd[k * XSTR + r0 + 2];
        ulonglong2 xc = *(const ulonglong2*)&sxd[k * XSTR + r0 + 4];
        ulonglong2 xd = *(const ulonglong2*)&sxd[k * XSTR + r0 + 6];
        FMA2(acc[0][0], xa.x, wv.x); FMA2(acc[0][1], xa.x, wv.y);
        FMA2(acc[1][0], xa.y, wv.x); FMA2(acc[1][1], xa.y, wv.y);
        FMA2(acc[2][0], xb.x, wv.x); FMA2(acc[2][1], xb.x, wv.y);
        FMA2(acc[3][0], xb.y, wv.x); FMA2(acc[3][1], xb.y, wv.y);
        FMA2(acc[4][0], xc.x, wv.x); FMA2(acc[4][1], xc.x, wv.y);
        FMA2(acc[5][0], xc.y, wv.x); FMA2(acc[5][1], xc.y, wv.y);
        FMA2(acc[6][0], xd.x, wv.x); FMA2(acc[6][1], xd.x, wv.y);
        FMA2(acc[7][0], xd.y, wv.x); FMA2(acc[7][1], xd.y, wv.y);
    }

#pragma unroll
    for (int r = 0; r < 8; r++) {
        int grow = rowbase + r0 + r;
        if (grow < n) {
            float4 o;
            asm("mov.b64 {%0, %1}, %2;" : "=f"(o.x), "=f"(o.y) : "l"(acc[r][0]));
            asm("mov.b64 {%0, %1}, %2;" : "=f"(o.z), "=f"(o.w) : "l"(acc[r][1]));
            g_h4[(size_t)grow * 32 + lane] = o;
        }
    }
}

// ---------------- attention dots: a_src/a_dst from h ----------------
__global__ void __launch_bounds__(256) k_att(
    const float* __restrict__ att_src, const float* __restrict__ att_dst, int n)
{
    const int lane = threadIdx.x & 31;
    const int i = (blockIdx.x * blockDim.x + threadIdx.x) >> 5;
    if (i >= n) return;
    float4 as4 = ((const float4*)att_src)[lane];
    float4 ad4 = ((const float4*)att_dst)[lane];
    float4 h4 = g_h4[(size_t)i * 32 + lane];
    float ps = h4.x * as4.x + h4.y * as4.y + h4.z * as4.z + h4.w * as4.w;
    float pd = h4.x * ad4.x + h4.y * ad4.y + h4.z * ad4.z + h4.w * ad4.w;
    const unsigned FULL = 0xffffffffu;
    ps += __shfl_xor_sync(FULL, ps, 4);
    pd += __shfl_xor_sync(FULL, pd, 4);
    ps += __shfl_xor_sync(FULL, ps, 2);
    pd += __shfl_xor_sync(FULL, pd, 2);
    ps += __shfl_xor_sync(FULL, ps, 1);
    pd += __shfl_xor_sync(FULL, pd, 1);
    if ((lane & 7) == 0) {
        ((float*)g_asrc4)[i * 4 + (lane >> 3)] = ps;
        ((float*)g_adst4)[i * 4 + (lane >> 3)] = pd;
    }
}

// ---------------- CSR build: histogram ----------------
__global__ void k_hist(const void* __restrict__ ei, int E) {
    int e = blockIdx.x * blockDim.x + threadIdx.x;
    if (e >= E) return;
    int dst = load_idx(ei, (long long)E + e, g_is64);
    atomicAdd(&g_cnt[dst], 1);
}

// ---------------- CSR build: scan (3 phases) ----------------
#define SCAN_BLK 1024
__global__ void k_scan1(int n) {
    __shared__ int sred[256];
    int b = blockIdx.x, t = threadIdx.x;
    int base = b * SCAN_BLK + t * 4;
    int s = 0;
#pragma unroll
    for (int u = 0; u < 4; u++) { int idx = base + u; if (idx < n) s += g_cnt[idx]; }
    sred[t] = s; __syncthreads();
    for (int off = 128; off > 0; off >>= 1) {
        if (t < off) sred[t] += sred[t + off];
        __syncthreads();
    }
    if (t == 0) g_part[b] = sred[0];
}
__global__ void k_scan2(int nb) {
    __shared__ int sp[128];
    int t = threadIdx.x;
    int v = (t < nb) ? g_part[t] : 0;
    sp[t] = v; __syncthreads();
    for (int off = 1; off < 128; off <<= 1) {
        int u = (t >= off) ? sp[t - off] : 0;
        __syncthreads();
        sp[t] += u;
        __syncthreads();
    }
    if (t < nb) g_part[t] = sp[t] - v;
}
__global__ void k_scan3(int n, int E) {
    __shared__ int ssum[256];
    int b = blockIdx.x, t = threadIdx.x;
    int base = b * SCAN_BLK + t * 4;
    int c[4]; int s = 0;
#pragma unroll
    for (int u = 0; u < 4; u++) { int idx = base + u; c[u] = (idx < n) ? g_cnt[idx] : 0; s += c[u]; }
    ssum[t] = s; __syncthreads();
    for (int off = 1; off < 256; off <<= 1) {
        int u = (t >= off) ? ssum[t - off] : 0;
        __syncthreads();
        ssum[t] += u;
        __syncthreads();
    }
    int run = g_part[b] + ssum[t] - s;
#pragma unroll
    for (int u = 0; u < 4; u++) {
        int idx = base + u;
        if (idx < n) { g_rowptr[idx] = run; g_cur[idx] = run; run += c[u]; }
    }
    if (b == 0 && t == 0) g_rowptr[n] = E;
}

// ---------------- CSR build: fill ----------------
__global__ void k_fill(const void* __restrict__ ei, int E) {
    int e = blockIdx.x * blockDim.x + threadIdx.x;
    if (e >= E) return;
    int is64 = g_is64;
    int src = load_idx(ei, e, is64);
    int dst = load_idx(ei, (long long)E + e, is64);
    int pos = atomicAdd(&g_cur[dst], 1);
    g_adj[pos] = src;
}

// ---------------- fused gather: softmax (no max shift) + aggregation + bias ----------------
// One warp per dst node. Lane l handles output cols 4l..4l+3 (head = l>>3).
// Logits are tiny (|alpha| < ~10, self-loop always present) so exp() without
// max-subtraction cannot overflow; result is mathematically identical.
__global__ void __launch_bounds__(256) k_gather(
    const float* __restrict__ bias, float* __restrict__ out, int n)
{
    __shared__ int   s_src[8][32];
    __shared__ float s_ex[8][32][4];
    const int lane = threadIdx.x & 31;
    const int wslot = threadIdx.x >> 5;
    const int i = (blockIdx.x * blockDim.x + threadIdx.x) >> 5;
    if (i >= n) return;
    const int hidx = lane >> 3;
    const unsigned FULL = 0xffffffffu;

    int start = g_rowptr[i];
    int deg = g_rowptr[i + 1] - start;
    float4 adst = g_adst4[i];

    float4 acc = make_float4(0.f, 0.f, 0.f, 0.f);
    float4 den = make_float4(0.f, 0.f, 0.f, 0.f);
    const float* exf = &s_ex[wslot][0][0];

    for (int base = 0; base < deg; base += 32) {
        int e = base + lane;
        int s = 0;
        float4 ex4 = make_float4(0.f, 0.f, 0.f, 0.f);
        if (e < deg) {
            s = g_adj[start + e];
            float4 as = g_asrc4[s];
            ex4.x = __expf(lrelu(as.x + adst.x));
            ex4.y = __expf(lrelu(as.y + adst.y));
            ex4.z = __expf(lrelu(as.z + adst.z));
            ex4.w = __expf(lrelu(as.w + adst.w));
            den.x += ex4.x; den.y += ex4.y; den.z += ex4.z; den.w += ex4.w;
        }
        s_src[wslot][lane] = s;
        s_ex[wslot][lane][0] = ex4.x; s_ex[wslot][lane][1] = ex4.y;
        s_ex[wslot][lane][2] = ex4.z; s_ex[wslot][lane][3] = ex4.w;
        __syncwarp();

        int cnt = min(32, deg - base);
        int j = 0;
        for (; j + 4 <= cnt; j += 4) {
            int s0 = s_src[wslot][j + 0], s1 = s_src[wslot][j + 1];
            int s2 = s_src[wslot][j + 2], s3 = s_src[wslot][j + 3];
            float w0 = exf[(j + 0) * 4 + hidx], w1 = exf[(j + 1) * 4 + hidx];
            float w2 = exf[(j + 2) * 4 + hidx], w3 = exf[(j + 3) * 4 + hidx];
            float4 h0 = g_h4[(size_t)s0 * 32 + lane];
            float4 h1 = g_h4[(size_t)s1 * 32 + lane];
            float4 h2 = g_h4[(size_t)s2 * 32 + lane];
            float4 h3 = g_h4[(size_t)s3 * 32 + lane];
            acc.x += w0 * h0.x; acc.y += w0 * h0.y; acc.z += w0 * h0.z; acc.w += w0 * h0.w;
            acc.x += w1 * h1.x; acc.y += w1 * h1.y; acc.z += w1 * h1.z; acc.w += w1 * h1.w;
            acc.x += w2 * h2.x; acc.y += w2 * h2.y; acc.z += w2 * h2.z; acc.w += w2 * h2.w;
            acc.x += w3 * h3.x; acc.y += w3 * h3.y; acc.z += w3 * h3.z; acc.w += w3 * h3.w;
        }
        for (; j < cnt; j++) {
            int sj = s_src[wslot][j];
            float w = exf[j * 4 + hidx];
            float4 hv = g_h4[(size_t)sj * 32 + lane];
            acc.x += w * hv.x; acc.y += w * hv.y; acc.z += w * hv.z; acc.w += w * hv.w;
        }
        __syncwarp();
    }

    // self-loop contribution
    float4 exs;
    {
        float4 as = g_asrc4[i];
        exs.x = __expf(lrelu(as.x + adst.x));
        exs.y = __expf(lrelu(as.y + adst.y));
        exs.z = __expf(lrelu(as.z + adst.z));
        exs.w = __expf(lrelu(as.w + adst.w));
    }
    {
        float ws = (hidx == 0) ? exs.x : (hidx == 1) ? exs.y : (hidx == 2) ? exs.z : exs.w;
        float4 hv = g_h4[(size_t)i * 32 + lane];
        acc.x += ws * hv.x; acc.y += ws * hv.y; acc.z += ws * hv.z; acc.w += ws * hv.w;
    }

#pragma unroll
    for (int off = 16; off > 0; off >>= 1) {
        den.x += __shfl_xor_sync(FULL, den.x, off);
        den.y += __shfl_xor_sync(FULL, den.y, off);
        den.z += __shfl_xor_sync(FULL, den.z, off);
        den.w += __shfl_xor_sync(FULL, den.w, off);
    }
    den.x += exs.x; den.y += exs.y; den.z += exs.z; den.w += exs.w;

    float dh = (hidx == 0) ? den.x : (hidx == 1) ? den.y : (hidx == 2) ? den.z : den.w;
    float inv = 1.f / (dh + 1e-16f);
    float4 b4 = ((const float4*)bias)[lane];
    float4 o;
    o.x = acc.x * inv + b4.x; o.y = acc.y * inv + b4.y;
    o.z = acc.z * inv + b4.z; o.w = acc.w * inv + b4.w;
    ((float4*)out)[(size_t)i * 32 + lane] = o;
}

// ---------------- launch ----------------
extern "C" void kernel_launch(void* const* d_in, const int* in_sizes, int n_in,
                              void* d_out, int out_size)
{
    const float* x       = (const float*)d_in[0];
    const void*  ei      = d_in[1];
    const float* W       = (const float*)d_in[2];
    const float* att_src = (const float*)d_in[3];
    const float* att_dst = (const float*)d_in[4];
    const float* bias    = (const float*)d_in[5];
    float* out = (float*)d_out;

    int n = in_sizes[0] / 128;
    int E = in_sizes[1] / 2;
    int nb = (n + SCAN_BLK - 1) / SCAN_BLK;
    const int GEMM_SMEM = 128 * XSTR * 8 + 128 * 128 * 4;   // 65536 + 65536 = 131072

    cudaFuncSetAttribute(k_gemm, cudaFuncAttributeMaxDynamicSharedMemorySize, GEMM_SMEM);

    k_init<<<(n + 255) / 256, 256>>>(ei, n);
    k_gemm<<<(n + GR - 1) / GR, 256, GEMM_SMEM>>>(x, W, n);
    k_att<<<(n * 32 + 255) / 256, 256>>>(att_src, att_dst, n);
    k_hist<<<(E + 255) / 256, 256>>>(ei, E);
    k_scan1<<<nb, 256>>>(n);
    k_scan2<<<1, 128>>>(nb);
    k_scan3<<<nb, 256>>>(n, E);
    k_fill<<<(E + 255) / 256, 256>>>(ei, E);
    k_gather<<<(n + 7) / 8, 256>>>(bias, out, n);
}

// round 7
// speedup vs baseline: 1.6314x; 1.3652x over previous
#include <cuda_runtime.h>
#include <math.h>

#define NMAX 100000
#define EMAX 1000000

// ---------------- scratch (static device arrays; no allocation) ----------------
__device__ float4 g_h4[(size_t)NMAX * 32];        // h [N,128] as float4
__device__ float4 g_asrc4[NMAX];                  // a_src [N,4]
__device__ float4 g_adst4[NMAX];                  // a_dst [N,4]
__device__ int    g_cnt[NMAX];                    // in-degree counts
__device__ int    g_rowptr[NMAX + 1];             // CSR row pointers (by dst)
__device__ int    g_cur[NMAX];                    // fill cursors
__device__ int    g_part[256];                    // scan block partials
__device__ int    g_adj[EMAX];                    // adjacency: src ids grouped by dst
__device__ int    g_is64;                         // edge_index dtype flag

// ---------------- helpers ----------------
__device__ __forceinline__ int load_idx(const void* ei, long long i, int is64) {
    if (is64) return (int)((const long long*)ei)[i];
    return ((const int*)ei)[i];
}
__device__ __forceinline__ float lrelu(float v) { return v >= 0.f ? v : 0.2f * v; }

#define FMA2(a, xx, ww) asm("fma.rn.f32x2 %0, %1, %2, %0;" : "+l"(a) : "l"(xx), "l"(ww))

// ---------------- init: zero counts + dtype detect ----------------
__global__ void k_init(const void* ei, int n) {
    int i = blockIdx.x * blockDim.x + threadIdx.x;
    if (i < n) g_cnt[i] = 0;
    if (i == 0) {
        const long long* p = (const long long*)ei;
        int ok = 1;
        for (int j = 0; j < 8; j++) {
            long long v = p[j];
            if (v < 0 || v >= n) ok = 0;
        }
        g_is64 = ok;
    }
}

// ---------------- shfl SGEMM: h = x @ W, fused attention dots ----------------
// 256 threads, 8 warps; warp handles 8 rows, lane covers cols lane*4..lane*4+3.
// W (64KB) is the ONLY smem stream (conflict-free per-lane LDS.128); x stays in
// registers, broadcast via shfl (MIO pipe, off the smem crossbar).
// Per k-step/warp: 8 shfl + 8 pack + 1 LDS.128 + 16 FMA2 = 33 instr / 1024 MACs.
#define GR 64
__global__ void __launch_bounds__(256) k_gemm(
    const float* __restrict__ x, const float* __restrict__ W,
    const float* __restrict__ att_src, const float* __restrict__ att_dst, int n)
{
    extern __shared__ float sw[];                 // [128][128] f32 (64KB)
    const int tid = threadIdx.x;
    {
        const float4* W4 = (const float4*)W;
        float4* s4 = (float4*)sw;
        for (int i = tid; i < 128 * 32; i += 256) s4[i] = W4[i];
    }
    __syncthreads();

    const int lane = tid & 31;
    const int wid = tid >> 5;
    const int rowbase = blockIdx.x * GR + wid * 8;
    const unsigned FULL = 0xffffffffu;
    const ulonglong2* swp = (const ulonglong2*)sw;   // k*32 + lane -> 4 cols (16B)
    const float4 as4 = ((const float4*)att_src)[lane];
    const float4 ad4 = ((const float4*)att_dst)[lane];

    // x rows in registers: xr[r][j] = x[rowbase+r][j*32 + lane]
    float xr[8][4];
#pragma unroll
    for (int r = 0; r < 8; r++) {
        int row = min(rowbase + r, n - 1);
        const float* xp = x + (size_t)row * 128;
#pragma unroll
        for (int j = 0; j < 4; j++) xr[r][j] = xp[j * 32 + lane];
    }

    unsigned long long acc[8][2];
#pragma unroll
    for (int r = 0; r < 8; r++) { acc[r][0] = 0ull; acc[r][1] = 0ull; }

    for (int j = 0; j < 4; j++) {
#pragma unroll
        for (int kk = 0; kk < 32; kk++) {
            ulonglong2 wv = swp[(j * 32 + kk) * 32 + lane];
#pragma unroll
            for (int r = 0; r < 8; r++) {
                float xk = __shfl_sync(FULL, xr[r][j], kk);
                unsigned long long xp2;
                asm("mov.b64 %0, {%1, %1};" : "=l"(xp2) : "f"(xk));
                FMA2(acc[r][0], xp2, wv.x);
                FMA2(acc[r][1], xp2, wv.y);
            }
        }
    }

#pragma unroll
    for (int r = 0; r < 8; r++) {
        int row = rowbase + r;
        if (row < n) {
            float4 h4;
            asm("mov.b64 {%0, %1}, %2;" : "=f"(h4.x), "=f"(h4.y) : "l"(acc[r][0]));
            asm("mov.b64 {%0, %1}, %2;" : "=f"(h4.z), "=f"(h4.w) : "l"(acc[r][1]));
            g_h4[(size_t)row * 32 + lane] = h4;
            float ps = h4.x * as4.x + h4.y * as4.y + h4.z * as4.z + h4.w * as4.w;
            float pd = h4.x * ad4.x + h4.y * ad4.y + h4.z * ad4.z + h4.w * ad4.w;
            ps += __shfl_xor_sync(FULL, ps, 4);
            pd += __shfl_xor_sync(FULL, pd, 4);
            ps += __shfl_xor_sync(FULL, ps, 2);
            pd += __shfl_xor_sync(FULL, pd, 2);
            ps += __shfl_xor_sync(FULL, ps, 1);
            pd += __shfl_xor_sync(FULL, pd, 1);
            if ((lane & 7) == 0) {
                ((float*)g_asrc4)[row * 4 + (lane >> 3)] = ps;
                ((float*)g_adst4)[row * 4 + (lane >> 3)] = pd;
            }
        }
    }
}

// ---------------- CSR build: histogram ----------------
__global__ void k_hist(const void* __restrict__ ei, int E) {
    int e = blockIdx.x * blockDim.x + threadIdx.x;
    if (e >= E) return;
    int dst = load_idx(ei, (long long)E + e, g_is64);
    atomicAdd(&g_cnt[dst], 1);
}

// ---------------- CSR build: scan (3 phases) ----------------
#define SCAN_BLK 1024
__global__ void k_scan1(int n) {
    __shared__ int sred[256];
    int b = blockIdx.x, t = threadIdx.x;
    int base = b * SCAN_BLK + t * 4;
    int s = 0;
#pragma unroll
    for (int u = 0; u < 4; u++) { int idx = base + u; if (idx < n) s += g_cnt[idx]; }
    sred[t] = s; __syncthreads();
    for (int off = 128; off > 0; off >>= 1) {
        if (t < off) sred[t] += sred[t + off];
        __syncthreads();
    }
    if (t == 0) g_part[b] = sred[0];
}
__global__ void k_scan2(int nb) {
    __shared__ int sp[128];
    int t = threadIdx.x;
    int v = (t < nb) ? g_part[t] : 0;
    sp[t] = v; __syncthreads();
    for (int off = 1; off < 128; off <<= 1) {
        int u = (t >= off) ? sp[t - off] : 0;
        __syncthreads();
        sp[t] += u;
        __syncthreads();
    }
    if (t < nb) g_part[t] = sp[t] - v;
}
__global__ void k_scan3(int n, int E) {
    __shared__ int ssum[256];
    int b = blockIdx.x, t = threadIdx.x;
    int base = b * SCAN_BLK + t * 4;
    int c[4]; int s = 0;
#pragma unroll
    for (int u = 0; u < 4; u++) { int idx = base + u; c[u] = (idx < n) ? g_cnt[idx] : 0; s += c[u]; }
    ssum[t] = s; __syncthreads();
    for (int off = 1; off < 256; off <<= 1) {
        int u = (t >= off) ? ssum[t - off] : 0;
        __syncthreads();
        ssum[t] += u;
        __syncthreads();
    }
    int run = g_part[b] + ssum[t] - s;
#pragma unroll
    for (int u = 0; u < 4; u++) {
        int idx = base + u;
        if (idx < n) { g_rowptr[idx] = run; g_cur[idx] = run; run += c[u]; }
    }
    if (b == 0 && t == 0) g_rowptr[n] = E;
}

// ---------------- CSR build: fill ----------------
__global__ void k_fill(const void* __restrict__ ei, int E) {
    int e = blockIdx.x * blockDim.x + threadIdx.x;
    if (e >= E) return;
    int is64 = g_is64;
    int src = load_idx(ei, e, is64);
    int dst = load_idx(ei, (long long)E + e, is64);
    int pos = atomicAdd(&g_cur[dst], 1);
    g_adj[pos] = src;
}

// ---------------- fused gather: softmax (no max shift) + aggregation + bias ----------------
// One warp per dst node. Lane l handles output cols 4l..4l+3 (head = l>>3).
// Logits are tiny (|alpha| < ~10) so exp() without max-subtraction cannot
// overflow; result is mathematically identical. Inner loop unroll 8 -> MLP 8.
__global__ void __launch_bounds__(256) k_gather(
    const float* __restrict__ bias, float* __restrict__ out, int n)
{
    __shared__ int   s_src[8][32];
    __shared__ float s_ex[8][32][4];
    const int lane = threadIdx.x & 31;
    const int wslot = threadIdx.x >> 5;
    const int i = (blockIdx.x * blockDim.x + threadIdx.x) >> 5;
    if (i >= n) return;
    const int hidx = lane >> 3;
    const unsigned FULL = 0xffffffffu;

    int start = g_rowptr[i];
    int deg = g_rowptr[i + 1] - start;
    float4 adst = g_adst4[i];

    float4 acc = make_float4(0.f, 0.f, 0.f, 0.f);
    float4 den = make_float4(0.f, 0.f, 0.f, 0.f);
    const float* exf = &s_ex[wslot][0][0];

    for (int base = 0; base < deg; base += 32) {
        int e = base + lane;
        int s = 0;
        float4 ex4 = make_float4(0.f, 0.f, 0.f, 0.f);
        if (e < deg) {
            s = g_adj[start + e];
            float4 as = g_asrc4[s];
            ex4.x = __expf(lrelu(as.x + adst.x));
            ex4.y = __expf(lrelu(as.y + adst.y));
            ex4.z = __expf(lrelu(as.z + adst.z));
            ex4.w = __expf(lrelu(as.w + adst.w));
            den.x += ex4.x; den.y += ex4.y; den.z += ex4.z; den.w += ex4.w;
        }
        s_src[wslot][lane] = s;
        s_ex[wslot][lane][0] = ex4.x; s_ex[wslot][lane][1] = ex4.y;
        s_ex[wslot][lane][2] = ex4.z; s_ex[wslot][lane][3] = ex4.w;
        __syncwarp();

        int cnt = min(32, deg - base);
        int j = 0;
        for (; j + 8 <= cnt; j += 8) {
            float4 hv[8];
            float wj[8];
#pragma unroll
            for (int u = 0; u < 8; u++) {
                int su = s_src[wslot][j + u];
                wj[u] = exf[(j + u) * 4 + hidx];
                hv[u] = g_h4[(size_t)su * 32 + lane];
            }
#pragma unroll
            for (int u = 0; u < 8; u++) {
                acc.x += wj[u] * hv[u].x; acc.y += wj[u] * hv[u].y;
                acc.z += wj[u] * hv[u].z; acc.w += wj[u] * hv[u].w;
            }
        }
        for (; j < cnt; j++) {
            int sj = s_src[wslot][j];
            float w = exf[j * 4 + hidx];
            float4 hv = g_h4[(size_t)sj * 32 + lane];
            acc.x += w * hv.x; acc.y += w * hv.y; acc.z += w * hv.z; acc.w += w * hv.w;
        }
        __syncwarp();
    }

    // self-loop contribution
    float4 exs;
    {
        float4 as = g_asrc4[i];
        exs.x = __expf(lrelu(as.x + adst.x));
        exs.y = __expf(lrelu(as.y + adst.y));
        exs.z = __expf(lrelu(as.z + adst.z));
        exs.w = __expf(lrelu(as.w + adst.w));
    }
    {
        float ws = (hidx == 0) ? exs.x : (hidx == 1) ? exs.y : (hidx == 2) ? exs.z : exs.w;
        float4 hv = g_h4[(size_t)i * 32 + lane];
        acc.x += ws * hv.x; acc.y += ws * hv.y; acc.z += ws * hv.z; acc.w += ws * hv.w;
    }

#pragma unroll
    for (int off = 16; off > 0; off >>= 1) {
        den.x += __shfl_xor_sync(FULL, den.x, off);
        den.y += __shfl_xor_sync(FULL, den.y, off);
        den.z += __shfl_xor_sync(FULL, den.z, off);
        den.w += __shfl_xor_sync(FULL, den.w, off);
    }
    den.x += exs.x; den.y += exs.y; den.z += exs.z; den.w += exs.w;

    float dh = (hidx == 0) ? den.x : (hidx == 1) ? den.y : (hidx == 2) ? den.z : den.w;
    float inv = 1.f / (dh + 1e-16f);
    float4 b4 = ((const float4*)bias)[lane];
    float4 o;
    o.x = acc.x * inv + b4.x; o.y = acc.y * inv + b4.y;
    o.z = acc.z * inv + b4.z; o.w = acc.w * inv + b4.w;
    ((float4*)out)[(size_t)i * 32 + lane] = o;
}

// ---------------- launch ----------------
extern "C" void kernel_launch(void* const* d_in, const int* in_sizes, int n_in,
                              void* d_out, int out_size)
{
    const float* x       = (const float*)d_in[0];
    const void*  ei      = d_in[1];
    const float* W       = (const float*)d_in[2];
    const float* att_src = (const float*)d_in[3];
    const float* att_dst = (const float*)d_in[4];
    const float* bias    = (const float*)d_in[5];
    float* out = (float*)d_out;

    int n = in_sizes[0] / 128;
    int E = in_sizes[1] / 2;
    int nb = (n + SCAN_BLK - 1) / SCAN_BLK;
    const int GEMM_SMEM = 128 * 128 * 4;   // 64KB: W only

    cudaFuncSetAttribute(k_gemm, cudaFuncAttributeMaxDynamicSharedMemorySize, GEMM_SMEM);

    k_init<<<(n + 255) / 256, 256>>>(ei, n);
    k_gemm<<<(n + GR - 1) / GR, 256, GEMM_SMEM>>>(x, W, att_src, att_dst, n);
    k_hist<<<(E + 255) / 256, 256>>>(ei, E);
    k_scan1<<<nb, 256>>>(n);
    k_scan2<<<1, 128>>>(nb);
    k_scan3<<<nb, 256>>>(n, E);
    k_fill<<<(E + 255) / 256, 256>>>(ei, E);
    k_gather<<<(n + 7) / 8, 256>>>(bias, out, n);
}